// round 6
// baseline (speedup 1.0000x reference)
#include <cuda_runtime.h>
#include <cuda_fp16.h>
#include <cstdint>

#define MAX_NODES 100000
#define D 128
#define EPT 7           // edges per thread (edge kernel)
#define EBLK 1024       // threads per block (edge kernel)

// Per-node projections: s as fp16 (smem-table source), d as fp32 with bias folded in.
__device__ __half g_s_h[MAX_NODES];
__device__ float  g_d[MAX_NODES];

// Kernel 1: 4 nodes per warp, all loads issued up-front for MLP=4.
__global__ void node_dots_kernel(const float4* __restrict__ x4,
                                 const float* __restrict__ W,
                                 const float* __restrict__ b,
                                 int n_nodes) {
    __shared__ float4 ws4[32];
    __shared__ float4 wd4[32];
    int tid = threadIdx.x;
    if (tid < 32) ws4[tid] = ((const float4*)W)[tid];
    else if (tid < 64) wd4[tid - 32] = ((const float4*)W)[tid - 32 + 32];
    __syncthreads();

    int lane = tid & 31;
    int gwarp = (blockIdx.x * blockDim.x + tid) >> 5;
    int base = gwarp * 4;
    if (base >= n_nodes) return;

    float4 a = ws4[lane];
    float4 c = wd4[lane];

    int n1 = base + 1, n2 = base + 2, n3 = base + 3;
    bool h1 = n1 < n_nodes, h2 = n2 < n_nodes, h3 = n3 < n_nodes;
    float4 v0 = x4[(size_t)base * 32 + lane];
    float4 v1 = h1 ? x4[(size_t)n1 * 32 + lane] : make_float4(0.f, 0.f, 0.f, 0.f);
    float4 v2 = h2 ? x4[(size_t)n2 * 32 + lane] : make_float4(0.f, 0.f, 0.f, 0.f);
    float4 v3 = h3 ? x4[(size_t)n3 * 32 + lane] : make_float4(0.f, 0.f, 0.f, 0.f);

    float s0 = v0.x * a.x + v0.y * a.y + v0.z * a.z + v0.w * a.w;
    float d0 = v0.x * c.x + v0.y * c.y + v0.z * c.z + v0.w * c.w;
    float s1 = v1.x * a.x + v1.y * a.y + v1.z * a.z + v1.w * a.w;
    float d1 = v1.x * c.x + v1.y * c.y + v1.z * c.z + v1.w * c.w;
    float s2 = v2.x * a.x + v2.y * a.y + v2.z * a.z + v2.w * a.w;
    float d2 = v2.x * c.x + v2.y * c.y + v2.z * c.z + v2.w * c.w;
    float s3 = v3.x * a.x + v3.y * a.y + v3.z * a.z + v3.w * a.w;
    float d3 = v3.x * c.x + v3.y * c.y + v3.z * c.z + v3.w * c.w;

    #pragma unroll
    for (int off = 16; off > 0; off >>= 1) {
        s0 += __shfl_down_sync(0xFFFFFFFFu, s0, off);
        d0 += __shfl_down_sync(0xFFFFFFFFu, d0, off);
        s1 += __shfl_down_sync(0xFFFFFFFFu, s1, off);
        d1 += __shfl_down_sync(0xFFFFFFFFu, d1, off);
        s2 += __shfl_down_sync(0xFFFFFFFFu, s2, off);
        d2 += __shfl_down_sync(0xFFFFFFFFu, d2, off);
        s3 += __shfl_down_sync(0xFFFFFFFFu, s3, off);
        d3 += __shfl_down_sync(0xFFFFFFFFu, d3, off);
    }
    if (lane == 0) {
        float b0 = __ldg(b);
        g_s_h[base] = __float2half(s0);
        g_d[base]   = d0 + b0;
        if (h1) { g_s_h[n1] = __float2half(s1); g_d[n1] = d1 + b0; }
        if (h2) { g_s_h[n2] = __float2half(s2); g_d[n2] = d2 + b0; }
        if (h3) { g_s_h[n3] = __float2half(s3); g_d[n3] = d3 + b0; }
    }
}

// Kernel 2: full fp16 s-table staged in shared memory (200KB). Per thread:
// load EPT edge indices + issue the fp32 d-gathers (L1/L2) BEFORE the table
// broadcast barrier so they overlap it; after the barrier, s comes from LDS
// (smem crossbar, no L1tex wavefronts). Output coalesced fp32 stores.
__global__ void __launch_bounds__(EBLK, 1)
edge_score_smem_kernel(const int* __restrict__ src,
                       const int* __restrict__ dst,
                       float* __restrict__ out,
                       int n_edges) {
    extern __shared__ __half s_sh[];
    int tid = threadIdx.x;
    int gtid = blockIdx.x * EBLK + tid;
    int stride = gridDim.x * EBLK;

    int   si[EPT];
    float dv[EPT];

    // Phase A: index loads + d-gathers (issued before the barrier; results
    // not consumed until after, so they overlap the table broadcast).
    #pragma unroll
    for (int k = 0; k < EPT; k++) {
        int e = gtid + k * stride;
        bool ok = e < n_edges;
        si[k]  = ok ? __ldcs(src + e) : 0;
        int di = ok ? __ldcs(dst + e) : 0;
        dv[k]  = g_d[di];
    }

    // Phase B: broadcast the fp16 s-table into smem (int4 = 8 halves/ld).
    {
        const int4* gs4 = reinterpret_cast<const int4*>(g_s_h);
        int4* ss4 = reinterpret_cast<int4*>(s_sh);
        const int n4 = MAX_NODES * 2 / 16;  // 12500
        for (int i = tid; i < n4; i += EBLK) ss4[i] = gs4[i];
    }
    __syncthreads();

    // Phase C: LDS s-gathers + sigmoid + coalesced stores.
    #pragma unroll
    for (int k = 0; k < EPT; k++) {
        int e = gtid + k * stride;
        if (e < n_edges) {
            float logit = __half2float(s_sh[si[k]]) + dv[k];
            out[e] = 1.0f / (1.0f + __expf(-logit));
        }
    }
}

extern "C" void kernel_launch(void* const* d_in, const int* in_sizes, int n_in,
                              void* d_out, int out_size) {
    const float* x   = (const float*)d_in[0];
    const int*   src = (const int*)d_in[1];
    const int*   dst = (const int*)d_in[2];
    const float* W   = (const float*)d_in[3];
    const float* b   = (const float*)d_in[4];
    float*       out = (float*)d_out;

    int n_nodes = in_sizes[0] / D;
    int n_edges = in_sizes[1];

    // Kernel 1: 4 nodes per warp, 8 warps/block -> 32 nodes/block
    {
        int nodes_per_block = 8 * 4;
        int blocks = (n_nodes + nodes_per_block - 1) / nodes_per_block;
        node_dots_kernel<<<blocks, 256>>>((const float4*)x, W, b, n_nodes);
    }
    // Kernel 2: smem-table edge scoring, one CTA per SM (200KB smem each)
    {
        const int smem_bytes = MAX_NODES * (int)sizeof(__half);  // 200000
        static bool attr_set = false;
        if (!attr_set) {
            cudaFuncSetAttribute(edge_score_smem_kernel,
                                 cudaFuncAttributeMaxDynamicSharedMemorySize,
                                 smem_bytes);
            attr_set = true;
        }
        int blocks = (n_edges + EBLK * EPT - 1) / (EBLK * EPT);
        if (blocks < 148) blocks = 148;
        edge_score_smem_kernel<<<blocks, EBLK, smem_bytes>>>(src, dst, out, n_edges);
    }
}